// round 14
// baseline (speedup 1.0000x reference)
#include <cuda_runtime.h>
#include <cuda_fp16.h>
#include <math.h>
#include <stdint.h>

#define NS 25
#define NQ 50
#define NV 75
#define SEQ 12
#define DIM 1152
#define HH 2
#define DH 576
#define NTUP 220
#define WAY 5
#define SHOT 5
#define KROWS (NQ*NTUP)      /* 11000 */
#define MPAD  11008
#define SKCOL (SHOT*NTUP)    /* 1100 per way */
#define NMRG  5500
#define NMRGP 5504
#define KPAD  1152
#define RS24  0.20412414523193154f

// ---------------- device scratch (zero-initialized; pads stay zero) ----------------
__device__ float g_pe[SEQ*DIM];
__device__ int   g_tuples[NTUP*3];
__device__ __align__(16) __half g_Ap[1024*DIM];
__device__ __align__(16) __half g_wT[6912*DIM];
__device__ __align__(16) __half g_P[(size_t)1024*6912];
__device__ __align__(16) __half g_qk[HH][(size_t)MPAD*DH];
__device__ __align__(16) __half g_skzm[HH][(size_t)NMRGP*DH];
__device__ __align__(16) __half g_sv[WAY*HH][(size_t)KPAD*DH];
__device__ __align__(16) __half g_svT[WAY*HH][(size_t)DH*KPAD];
__device__ __align__(16) __half g_qv[(size_t)KROWS*DIM];
__device__ __align__(16) __half g_attn[WAY*HH][(size_t)MPAD*KPAD];
__device__ float g_rowsum[WAY*HH][MPAD];

// ---------------- helpers ----------------
__device__ __forceinline__ uint32_t smem_u32(const void* p){
    uint32_t a;
    asm("{ .reg .u64 t; cvta.to.shared.u64 t, %1; cvt.u32.u64 %0, t; }" : "=r"(a) : "l"(p));
    return a;
}
#define SW128(x) ((x) ^ (((x)>>3)&0x70))

__device__ __forceinline__ void ldm4(uint32_t* r, uint32_t addr){
    asm volatile("ldmatrix.sync.aligned.m8n8.x4.shared.b16 {%0,%1,%2,%3}, [%4];"
        : "=r"(r[0]), "=r"(r[1]), "=r"(r[2]), "=r"(r[3]) : "r"(addr));
}
__device__ __forceinline__ void mma16816h(uint32_t* c, const uint32_t* a, uint32_t b0, uint32_t b1){
    asm volatile("mma.sync.aligned.m16n8k16.row.col.f16.f16.f16.f16 "
        "{%0,%1}, {%2,%3,%4,%5}, {%6,%7}, {%0,%1};"
        : "+r"(c[0]), "+r"(c[1])
        : "r"(a[0]), "r"(a[1]), "r"(a[2]), "r"(a[3]), "r"(b0), "r"(b1));
}
__device__ __forceinline__ void cpa16(uint32_t dst, const void* src){
    asm volatile("cp.async.cg.shared.global [%0], [%1], 16;" :: "r"(dst), "l"(src));
}
__device__ __forceinline__ uint32_t h2ex2(uint32_t h){
    uint32_t o;
    asm("ex2.approx.f16x2 %0, %1;" : "=r"(o) : "r"(h));
    return o;
}

// ---------------- init ----------------
__global__ void k_init(float* out) {
    int gi = blockIdx.x*256 + threadIdx.x;
    if (gi < WAY*HH*MPAD) ((float*)g_rowsum)[gi] = 0.f;
    if (blockIdx.x == 0) {
        int tid = threadIdx.x;
        for (int i = tid; i < SEQ*576; i += 256) {
            int p = i / 576, j = i % 576;
            double dv = exp(-(double)(2*j) * (log(10000.0) / 1152.0));
            double ang = (double)p * dv;
            g_pe[p*DIM + 2*j]     = (float)(sin(ang) * 0.1);
            g_pe[p*DIM + 2*j + 1] = (float)(cos(ang) * 0.1);
        }
        if (tid < NQ*WAY) out[tid] = 0.f;
        if (tid == 0) {
            int idx = 0;
            for (int a = 0; a < SEQ; a++)
                for (int b = a+1; b < SEQ; b++)
                    for (int c = b+1; c < SEQ; c++) {
                        g_tuples[idx*3+0]=a; g_tuples[idx*3+1]=b; g_tuples[idx*3+2]=c; idx++;
                    }
        }
    }
}

__global__ __launch_bounds__(128) void k_prepA(const float* __restrict__ sup,
                                               const float* __restrict__ qry){
    int m = blockIdx.x; int v = m/SEQ, f = m%SEQ;
    const float* src = (v < NS) ? sup + (size_t)m*DIM
                                : qry + ((size_t)(v-NS)*SEQ + f)*DIM;
    for (int i = threadIdx.x; i < DIM; i += 128)
        g_Ap[(size_t)m*DIM + i] = __float2half(src[i] + g_pe[f*DIM + i]);
}

__global__ __launch_bounds__(256) void k_transW(const float* __restrict__ kw,
                                                const float* __restrict__ vw){
    __shared__ float t[32][33];
    int z = blockIdx.z; int j = z>>1, which = z&1;
    const float* W = which ? vw : kw;
    int o0 = blockIdx.x*32, k0 = blockIdx.y*32;
    int tx = threadIdx.x & 31, ty = threadIdx.x >> 5;
    #pragma unroll
    for (int r = 0; r < 4; r++)
        t[ty + r*8][tx] = W[(size_t)(j*1152 + k0 + ty + r*8)*1152 + o0 + tx];
    __syncthreads();
    #pragma unroll
    for (int r = 0; r < 4; r++)
        g_wT[(size_t)(j*2304 + which*1152 + o0 + ty + r*8)*1152 + k0 + tx]
            = __float2half(t[tx][ty + r*8]);
}

// ---------------- V transpose: sv[z][1152p x 576] -> svT[z][576 x 1152] ----------------
__global__ __launch_bounds__(256) void k_transV(){
    __shared__ __half t[64][65];
    const int z = blockIdx.z;
    const int r0 = blockIdx.x * 64;
    const int c0 = blockIdx.y * 64;
    const int tx = threadIdx.x & 31, ty = threadIdx.x >> 5;
    const __half* sv = g_sv[z];
    __half* svT = g_svT[z];
    #pragma unroll
    for (int r = 0; r < 8; r++){
        int row = ty + r*8;
        __half2 v = *(const __half2*)(sv + (size_t)(r0 + row)*DH + c0 + tx*2);
        t[row][tx*2]   = __low2half(v);
        t[row][tx*2+1] = __high2half(v);
    }
    __syncthreads();
    #pragma unroll
    for (int c = 0; c < 8; c++){
        int col = ty + c*8;
        __half2 v = __halves2half2(t[tx*2][col], t[tx*2+1][col]);
        *(__half2*)(svT + (size_t)(c0 + col)*KPAD + r0 + tx*2) = v;
    }
}

// ---------------- f16 NT GEMM, f16 acc, pipelined cp.async ----------------
// C[M,N] = A[M,K] @ B[N,K]^T. CTA tile (GM*WM) x (GN*WN). 8 warps. K = KT*64.
// OT=0: raw f16 store. OT=1: merged-scores epilogue. OT=2: normalize + fused logits.
template<int OT, int WM, int WN, int GM, int GN, int STAGES>
__global__ __launch_bounds__(256, 2) void k_gemmh(
    const __half* __restrict__ A, int lda, int amod, size_t sA,
    const __half* __restrict__ B, int ldb, size_t sB,
    void* __restrict__ Cv, int ldc, size_t sC, int KT,
    const __half* __restrict__ qv, float* __restrict__ out, float* __restrict__ rsum)
{
    constexpr int BM  = GM*WM;
    constexpr int BN  = GN*WN;
    constexpr int ASZ = BM*128;
    constexpr int BSZ = BN*128;
    constexpr int STG = ASZ + BSZ;
    extern __shared__ char smem[];
    const int tid = threadIdx.x, wid = tid>>5, lane = tid&31;
    const int wm = wid % GM, wn = wid / GM;
    const int z = blockIdx.z;
    A += (size_t)(amod ? (z % amod) : z) * sA;
    B += (size_t)z * sB;
    const int m0 = blockIdx.y*BM, n0 = blockIdx.x*BN;
    const uint32_t sbase = smem_u32(smem);
    const int lrow = tid >> 3, lch = tid & 7;

    uint32_t acc[WM/16][WN/8][2];
    #pragma unroll
    for (int i=0;i<WM/16;i++)
        #pragma unroll
        for (int j=0;j<WN/8;j++){ acc[i][j][0]=0u; acc[i][j][1]=0u; }

    auto load_tile = [&](int kt, int buf){
        const __half* Ab = A + (size_t)m0*lda + kt*64;
        const __half* Bb = B + (size_t)n0*ldb + kt*64;
        uint32_t da = sbase + buf*STG;
        uint32_t db = da + ASZ;
        #pragma unroll
        for (int c = 0; c < BM/32; c++){
            int row = lrow + c*32;
            cpa16(da + SW128(row*128 + lch*16), Ab + (size_t)row*lda + lch*8);
        }
        #pragma unroll
        for (int c = 0; c < BN/32; c++){
            int row = lrow + c*32;
            cpa16(db + SW128(row*128 + lch*16), Bb + (size_t)row*ldb + lch*8);
        }
        asm volatile("cp.async.commit_group;");
    };

    #pragma unroll
    for (int s = 0; s < STAGES-1; s++) load_tile(s, s);

    for (int kt = 0; kt < KT; kt++){
        if (kt + STAGES-1 < KT) load_tile(kt + STAGES-1, (kt + STAGES-1) % STAGES);
        if (kt + 1 >= KT)      asm volatile("cp.async.wait_group 0;");
        else if (STAGES == 2 || kt + 2 >= KT) asm volatile("cp.async.wait_group 1;");
        else                   asm volatile("cp.async.wait_group 2;");
        __syncthreads();
        const uint32_t sA_ = sbase + (kt % STAGES)*STG;
        const uint32_t sB_ = sA_ + ASZ;
        #pragma unroll
        for (int kk = 0; kk < 4; kk++){
            const int colb = kk*32 + ((lane >> 4) << 4);
            uint32_t a[WM/16][4], b[WN/16][4];
            #pragma unroll
            for (int i = 0; i < WM/16; i++)
                ldm4(a[i], sA_ + SW128((wm*WM + i*16 + (lane & 15))*128 + colb));
            #pragma unroll
            for (int j = 0; j < WN/16; j++)
                ldm4(b[j], sB_ + SW128((wn*WN + j*16 + (lane & 15))*128 + colb));
            #pragma unroll
            for (int i = 0; i < WM/16; i++)
                #pragma unroll
                for (int jj = 0; jj < WN/8; jj++)
                    mma16816h(acc[i][jj], a[i], b[jj>>1][jj&1], b[jj>>1][2+(jj&1)]);
        }
        __syncthreads();
    }

    if (OT == 0) {
        __half* C = (__half*)Cv + (size_t)z * sC;
        #pragma unroll
        for (int i = 0; i < WM/16; i++){
            int r0 = m0 + wm*WM + i*16 + (lane >> 2);
            #pragma unroll
            for (int jj = 0; jj < WN/8; jj++){
                int cc = n0 + wn*WN + jj*8 + (lane & 3)*2;
                *(uint32_t*)(C + (size_t)r0*ldc + cc)     = acc[i][jj][0];
                *(uint32_t*)(C + (size_t)(r0+8)*ldc + cc) = acc[i][jj][1];
            }
        }
    } else if (OT == 1) {
        const int h = z;
        const uint32_t L2E = 0x3dc53dc5u;  // half2(1.4427)
        const int wA = n0 / SKCOL;
        const int bnd = (wA + 1) * SKCOL;
        float rsA[WM/16][2], rsB[WM/16][2];
        #pragma unroll
        for (int i=0;i<WM/16;i++){ rsA[i][0]=0.f; rsA[i][1]=0.f; rsB[i][0]=0.f; rsB[i][1]=0.f; }
        #pragma unroll
        for (int i = 0; i < WM/16; i++){
            int r0 = m0 + wm*WM + i*16 + (lane >> 2);
            #pragma unroll
            for (int jj = 0; jj < WN/8; jj++){
                int cc = n0 + wn*WN + jj*8 + (lane & 3)*2;
                if (cc < NMRG) {
                    int hiw = (cc >= bnd);
                    int w = wA + hiw;
                    int lc = cc - w*SKCOL;
                    __half* C = g_attn[w*2 + h];
                    __half2 m0h = __hmul2(*(__half2*)&acc[i][jj][0], *(__half2*)&L2E);
                    __half2 m1h = __hmul2(*(__half2*)&acc[i][jj][1], *(__half2*)&L2E);
                    uint32_t e0 = h2ex2(*(uint32_t*)&m0h);
                    uint32_t e1 = h2ex2(*(uint32_t*)&m1h);
                    *(uint32_t*)(C + (size_t)r0*KPAD + lc)     = e0;
                    *(uint32_t*)(C + (size_t)(r0+8)*KPAD + lc) = e1;
                    float2 f0 = __half22float2(*(__half2*)&e0);
                    float2 f1 = __half22float2(*(__half2*)&e1);
                    if (hiw) { rsB[i][0] += f0.x + f0.y; rsB[i][1] += f1.x + f1.y; }
                    else     { rsA[i][0] += f0.x + f0.y; rsA[i][1] += f1.x + f1.y; }
                }
            }
        }
        #pragma unroll
        for (int i = 0; i < WM/16; i++){
            int r0 = m0 + wm*WM + i*16 + (lane >> 2);
            #pragma unroll
            for (int rr = 0; rr < 2; rr++){
                float sa = rsA[i][rr], sb = rsB[i][rr];
                sa += __shfl_xor_sync(0xffffffffu, sa, 1);
                sa += __shfl_xor_sync(0xffffffffu, sa, 2);
                sb += __shfl_xor_sync(0xffffffffu, sb, 1);
                sb += __shfl_xor_sync(0xffffffffu, sb, 2);
                if ((lane & 3) == 0) {
                    int row = r0 + rr*8;
                    if (sa != 0.f) atomicAdd(&g_rowsum[wA*2 + h][row], sa);
                    if (sb != 0.f) atomicAdd(&g_rowsum[(wA+1)*2 + h][row], sb);
                }
            }
        }
    } else {
        const int w = z >> 1, h = z & 1;
        const int q0 = m0 / NTUP;
        const int qb = (q0 + 1) * NTUP;
        const float* rz = rsum + (size_t)z * MPAD;
        float s0 = 0.f, s1 = 0.f;
        #pragma unroll
        for (int i = 0; i < WM/16; i++){
            int rb = m0 + wm*WM + i*16 + (lane >> 2);
            #pragma unroll
            for (int rr = 0; rr < 2; rr++){
                int row = rb + rr*8;
                if (row < KROWS) {
                    const float inv = 1.f / rz[row];
                    const __half* qrow = qv + (size_t)row*DIM + h*DH;
                    float part = 0.f;
                    #pragma unroll
                    for (int jj = 0; jj < WN/8; jj++){
                        int cc = n0 + wn*WN + jj*8 + (lane & 3)*2;
                        float2 v = __half22float2(*(__half2*)&acc[i][jj][rr]);
                        float2 q2 = __half22float2(*(const __half2*)(qrow + cc));
                        float d0 = q2.x - v.x*inv;
                        float d1 = q2.y - v.y*inv;
                        part += d0*d0 + d1*d1;
                    }
                    if (row >= qb) s1 += part; else s0 += part;
                }
            }
        }
        float* red = (float*)smem;
        red[tid] = s0; red[256 + tid] = s1;
        __syncthreads();
        #pragma unroll
        for (int st = 128; st > 0; st >>= 1){
            if (tid < st) { red[tid] += red[tid+st]; red[256+tid] += red[256+tid+st]; }
            __syncthreads();
        }
        if (tid == 0 && red[0]   != 0.f) atomicAdd(&out[q0*WAY + w], -red[0]   * (1.f/NTUP));
        if (tid == 1 && q0 + 1 < NQ && red[256] != 0.f)
            atomicAdd(&out[(q0+1)*WAY + w], -red[256] * (1.f/NTUP));
    }
}

// ---------------- tuple combine + bias + LayerNorm (split: bias selects row range) ----------------
__global__ __launch_bounds__(192) void k_combine(
    const float* __restrict__ kb, const float* __restrict__ vb,
    const float* __restrict__ lg, const float* __restrict__ lb, int bbase)
{
    const int bid = blockIdx.x + bbase;
    const int v = bid / NTUP, t = bid % NTUP;
    const int tid = threadIdx.x, lane = tid & 31, wrp = tid >> 5;
    __shared__ float redS[6], redQ[6];
    __shared__ int fr[3];
    if (tid < 3) fr[tid] = g_tuples[t*3 + tid];
    __syncthreads();

    const __half2* Pb[3];
    #pragma unroll
    for (int j = 0; j < 3; j++)
        Pb[j] = (const __half2*)(g_P + (size_t)(v*SEQ + fr[j])*6912) + j*1152;

    float2 kv[3], vv[3];
    float lsum = 0.f, lsq = 0.f;
    #pragma unroll
    for (int ii = 0; ii < 3; ii++) {
        int i = tid + ii*192;
        int d0 = 2*i;
        float2 ka = *(const float2*)(kb + d0);
        float2 va = *(const float2*)(vb + d0);
        #pragma unroll
        for (int j = 0; j < 3; j++) {
            float2 pk = __half22float2(Pb[j][i]);
            float2 pv = __half22float2(Pb[j][576 + i]);
            ka.x += pk.x; ka.y += pk.y;
            va.x += pv.x; va.y += pv.y;
        }
        kv[ii] = ka; vv[ii] = va;
        lsum += ka.x + ka.y;
        lsq  += ka.x*ka.x + ka.y*ka.y;
    }
    #pragma unroll
    for (int o = 16; o; o >>= 1) {
        lsum += __shfl_xor_sync(0xffffffffu, lsum, o);
        lsq  += __shfl_xor_sync(0xffffffffu, lsq,  o);
    }
    if (lane == 0) { redS[wrp] = lsum; redQ[wrp] = lsq; }
    __syncthreads();
    if (tid == 0) {
        float s = 0.f, q = 0.f;
        #pragma unroll
        for (int wv = 0; wv < 6; wv++) { s += redS[wv]; q += redQ[wv]; }
        redS[0] = s; redQ[0] = q;
    }
    __syncthreads();
    float mu = redS[0] * (1.f/1152.f);
    float var = redQ[0] * (1.f/1152.f) - mu*mu;
    float rstd = rsqrtf(var + 1e-5f);

    int w = 0, s = 0;
    if (v < NS) { w = v / SHOT; s = v % SHOT; }
    #pragma unroll
    for (int ii = 0; ii < 3; ii++) {
        int i = tid + ii*192;
        int d0 = 2*i;
        int h = (d0 >= DH) ? 1 : 0;
        int dd = d0 - h*DH;
        float2 g = *(const float2*)(lg + d0);
        float2 b = *(const float2*)(lb + d0);
        float ox = ((kv[ii].x - mu)*rstd*g.x + b.x) * RS24;
        float oy = ((kv[ii].y - mu)*rstd*g.y + b.y) * RS24;
        __half2 oh = __floats2half2_rn(ox, oy);
        __half2 vh = __floats2half2_rn(vv[ii].x, vv[ii].y);
        if (v < NS) {
            int row = s*NTUP + t;
            *(__half2*)&g_skzm[h][(size_t)(w*SKCOL + row)*DH + dd] = oh;
            *(__half2*)&g_sv[w*2 + h][(size_t)row*DH + dd] = vh;
        } else {
            *(__half2*)&g_qk[h][(size_t)((v-NS)*NTUP + t)*DH + dd] = oh;
            *(__half2*)&g_qv[(size_t)((v-NS)*NTUP + t)*DIM + d0] = vh;
        }
    }
}

// ---------------- launch ----------------
extern "C" void kernel_launch(void* const* d_in, const int* in_sizes, int n_in,
                              void* d_out, int out_size)
{
    const float* support = (const float*)d_in[0];
    const float* queries = (const float*)d_in[1];
    const float* k_w  = (const float*)d_in[3];
    const float* k_b  = (const float*)d_in[4];
    const float* v_w  = (const float*)d_in[5];
    const float* v_b  = (const float*)d_in[6];
    const float* ln_g = (const float*)d_in[7];
    const float* ln_b = (const float*)d_in[8];
    float* out = (float*)d_out;

    void *pAp, *pWT, *pP, *pQK, *pSKZM, *pSVT, *pATT, *pQV, *pRS;
    cudaGetSymbolAddress(&pAp,   g_Ap);
    cudaGetSymbolAddress(&pWT,   g_wT);
    cudaGetSymbolAddress(&pP,    g_P);
    cudaGetSymbolAddress(&pQK,   g_qk);
    cudaGetSymbolAddress(&pSKZM, g_skzm);
    cudaGetSymbolAddress(&pSVT,  g_svT);
    cudaGetSymbolAddress(&pATT,  g_attn);
    cudaGetSymbolAddress(&pQV,   g_qv);
    cudaGetSymbolAddress(&pRS,   g_rowsum);

    auto gemm_pp = k_gemmh<0,32,32,2,4,3>;   // proj, 64x128 tiles
    auto gemm_sc = k_gemmh<1,32,64,4,2,3>;   // merged scores, 128x128 tiles
    auto gemm_pr = k_gemmh<2,32,32,4,2,3>;   // proto, 128x64 tiles (low tail waste)
    cudaFuncSetAttribute(gemm_pp, cudaFuncAttributeMaxDynamicSharedMemorySize, 3*24576);
    cudaFuncSetAttribute(gemm_sc, cudaFuncAttributeMaxDynamicSharedMemorySize, 3*32768);
    cudaFuncSetAttribute(gemm_pr, cudaFuncAttributeMaxDynamicSharedMemorySize, 3*24576);

    // fork/join side stream (capture-legal; proven R8/R10/R12/R13)
    cudaStream_t s1;
    cudaStreamCreateWithFlags(&s1, cudaStreamNonBlocking);
    cudaEvent_t e0, eA, ePA, eT;
    cudaEventCreateWithFlags(&e0,  cudaEventDisableTiming);
    cudaEventCreateWithFlags(&eA,  cudaEventDisableTiming);
    cudaEventCreateWithFlags(&ePA, cudaEventDisableTiming);
    cudaEventCreateWithFlags(&eT,  cudaEventDisableTiming);

    k_init<<<432, 256>>>(out);
    cudaEventRecord(e0, 0);

    // side stream: A-prep (overlaps transW on main)
    cudaStreamWaitEvent(s1, e0, 0);
    k_prepA<<<NV*SEQ, 128, 0, s1>>>(support, queries);
    cudaEventRecord(eA, s1);

    k_transW<<<dim3(36, 36, 6), 256>>>(k_w, v_w);
    cudaStreamWaitEvent(0, eA, 0);

    // projA: rows [0,320) — covers all support rows (v<25 => row<300)
    gemm_pp<<<dim3(54, 5, 1), 256, 3*24576>>>(
        (const __half*)pAp, DIM, 1, 0,
        (const __half*)pWT, DIM, 0,
        pP, 6912, 0, 18, nullptr, nullptr, nullptr);
    cudaEventRecord(ePA, 0);

    // side: combine for support (writes skzm, sv) + V transpose — overlaps projB
    cudaStreamWaitEvent(s1, ePA, 0);
    k_combine<<<NS*NTUP, 192, 0, s1>>>(k_b, v_b, ln_g, ln_b, 0);
    k_transV<<<dim3(18, 9, WAY*HH), 256, 0, s1>>>();
    cudaEventRecord(eT, s1);

    // projB: rows [320,960)
    gemm_pp<<<dim3(54, 10, 1), 256, 3*24576>>>(
        (const __half*)pAp + (size_t)320*DIM, DIM, 1, 0,
        (const __half*)pWT, DIM, 0,
        (__half*)pP + (size_t)320*6912, 6912, 0, 18, nullptr, nullptr, nullptr);

    // combine for queries (writes qk, qv)
    k_combine<<<NQ*NTUP, 192>>>(k_b, v_b, ln_g, ln_b, NS*NTUP);

    // scores needs skzm (side) + qk (main)
    cudaStreamWaitEvent(0, eT, 0);
    gemm_sc<<<dim3(NMRGP/128, MPAD/128, HH), 256, 3*32768>>>(
        (const __half*)pQK, DH, 2, (size_t)MPAD*DH,
        (const __half*)pSKZM, DH, (size_t)NMRGP*DH,
        nullptr, 0, 0, 9, nullptr, nullptr, nullptr);

    // proto + normalize + fused logits (128x64 tiles)
    gemm_pr<<<dim3(9, 86, WAY*HH), 256, 3*24576>>>(
        (const __half*)pATT, KPAD, 0, (size_t)MPAD*KPAD,
        (const __half*)pSVT, KPAD, (size_t)DH*KPAD,
        nullptr, 0, 0, 18, (const __half*)pQV, out, (float*)pRS);
}

// round 15
// speedup vs baseline: 1.0651x; 1.0651x over previous
#include <cuda_runtime.h>
#include <cuda_fp16.h>
#include <math.h>
#include <stdint.h>

#define NS 25
#define NQ 50
#define NV 75
#define SEQ 12
#define DIM 1152
#define HH 2
#define DH 576
#define NTUP 220
#define WAY 5
#define SHOT 5
#define KROWS (NQ*NTUP)      /* 11000 */
#define MPAD  11008
#define SKCOL (SHOT*NTUP)    /* 1100 per way */
#define NMRG  5500
#define NMRGP 5504
#define KPAD  1152
#define RS24  0.20412414523193154f

// ---------------- device scratch (zero-initialized; pads stay zero) ----------------
__device__ float g_pe[SEQ*DIM];
__device__ int   g_tuples[NTUP*3];
__device__ __align__(16) __half g_Ap[1024*DIM];
__device__ __align__(16) __half g_wT[6912*DIM];
__device__ __align__(16) __half g_P[(size_t)1024*6912];
__device__ __align__(16) __half g_qk[HH][(size_t)MPAD*DH];
__device__ __align__(16) __half g_skzm[HH][(size_t)NMRGP*DH];
__device__ __align__(16) __half g_sv[WAY*HH][(size_t)KPAD*DH];
__device__ __align__(16) __half g_svT[WAY*HH][(size_t)DH*KPAD];
__device__ __align__(16) __half g_qv[(size_t)KROWS*DIM];
__device__ __align__(16) __half g_attn[WAY*HH][(size_t)MPAD*KPAD];
__device__ float g_rowsum[WAY*HH][MPAD];

// ---------------- helpers ----------------
__device__ __forceinline__ uint32_t smem_u32(const void* p){
    uint32_t a;
    asm("{ .reg .u64 t; cvta.to.shared.u64 t, %1; cvt.u32.u64 %0, t; }" : "=r"(a) : "l"(p));
    return a;
}
#define SW128(x) ((x) ^ (((x)>>3)&0x70))

__device__ __forceinline__ void ldm4(uint32_t* r, uint32_t addr){
    asm volatile("ldmatrix.sync.aligned.m8n8.x4.shared.b16 {%0,%1,%2,%3}, [%4];"
        : "=r"(r[0]), "=r"(r[1]), "=r"(r[2]), "=r"(r[3]) : "r"(addr));
}
__device__ __forceinline__ void mma16816h(uint32_t* c, const uint32_t* a, uint32_t b0, uint32_t b1){
    asm volatile("mma.sync.aligned.m16n8k16.row.col.f16.f16.f16.f16 "
        "{%0,%1}, {%2,%3,%4,%5}, {%6,%7}, {%0,%1};"
        : "+r"(c[0]), "+r"(c[1])
        : "r"(a[0]), "r"(a[1]), "r"(a[2]), "r"(a[3]), "r"(b0), "r"(b1));
}
__device__ __forceinline__ void cpa16(uint32_t dst, const void* src){
    asm volatile("cp.async.cg.shared.global [%0], [%1], 16;" :: "r"(dst), "l"(src));
}
__device__ __forceinline__ uint32_t h2ex2(uint32_t h){
    uint32_t o;
    asm("ex2.approx.f16x2 %0, %1;" : "=r"(o) : "r"(h));
    return o;
}

// ---------------- init ----------------
__global__ void k_init(float* out) {
    int gi = blockIdx.x*256 + threadIdx.x;
    if (gi < WAY*HH*MPAD) ((float*)g_rowsum)[gi] = 0.f;
    if (blockIdx.x == 0) {
        int tid = threadIdx.x;
        for (int i = tid; i < SEQ*576; i += 256) {
            int p = i / 576, j = i % 576;
            double dv = exp(-(double)(2*j) * (log(10000.0) / 1152.0));
            double ang = (double)p * dv;
            g_pe[p*DIM + 2*j]     = (float)(sin(ang) * 0.1);
            g_pe[p*DIM + 2*j + 1] = (float)(cos(ang) * 0.1);
        }
        if (tid < NQ*WAY) out[tid] = 0.f;
        if (tid == 0) {
            int idx = 0;
            for (int a = 0; a < SEQ; a++)
                for (int b = a+1; b < SEQ; b++)
                    for (int c = b+1; c < SEQ; c++) {
                        g_tuples[idx*3+0]=a; g_tuples[idx*3+1]=b; g_tuples[idx*3+2]=c; idx++;
                    }
        }
    }
}

__global__ __launch_bounds__(128) void k_prepA(const float* __restrict__ sup,
                                               const float* __restrict__ qry){
    int m = blockIdx.x; int v = m/SEQ, f = m%SEQ;
    const float* src = (v < NS) ? sup + (size_t)m*DIM
                                : qry + ((size_t)(v-NS)*SEQ + f)*DIM;
    for (int i = threadIdx.x; i < DIM; i += 128)
        g_Ap[(size_t)m*DIM + i] = __float2half(src[i] + g_pe[f*DIM + i]);
}

__global__ __launch_bounds__(256) void k_transW(const float* __restrict__ kw,
                                                const float* __restrict__ vw){
    __shared__ float t[32][33];
    int z = blockIdx.z; int j = z>>1, which = z&1;
    const float* W = which ? vw : kw;
    int o0 = blockIdx.x*32, k0 = blockIdx.y*32;
    int tx = threadIdx.x & 31, ty = threadIdx.x >> 5;
    #pragma unroll
    for (int r = 0; r < 4; r++)
        t[ty + r*8][tx] = W[(size_t)(j*1152 + k0 + ty + r*8)*1152 + o0 + tx];
    __syncthreads();
    #pragma unroll
    for (int r = 0; r < 4; r++)
        g_wT[(size_t)(j*2304 + which*1152 + o0 + ty + r*8)*1152 + k0 + tx]
            = __float2half(t[tx][ty + r*8]);
}

// ---------------- V transpose: sv[z][1152p x 576] -> svT[z][576 x 1152] ----------------
__global__ __launch_bounds__(256) void k_transV(){
    __shared__ __half t[64][65];
    const int z = blockIdx.z;
    const int r0 = blockIdx.x * 64;
    const int c0 = blockIdx.y * 64;
    const int tx = threadIdx.x & 31, ty = threadIdx.x >> 5;
    const __half* sv = g_sv[z];
    __half* svT = g_svT[z];
    #pragma unroll
    for (int r = 0; r < 8; r++){
        int row = ty + r*8;
        __half2 v = *(const __half2*)(sv + (size_t)(r0 + row)*DH + c0 + tx*2);
        t[row][tx*2]   = __low2half(v);
        t[row][tx*2+1] = __high2half(v);
    }
    __syncthreads();
    #pragma unroll
    for (int c = 0; c < 8; c++){
        int col = ty + c*8;
        __half2 v = __halves2half2(t[tx*2][col], t[tx*2+1][col]);
        *(__half2*)(svT + (size_t)(c0 + col)*KPAD + r0 + tx*2) = v;
    }
}

// ---------------- f16 NT GEMM, f16 acc, pipelined cp.async ----------------
// C[M,N] = A[M,K] @ B[N,K]^T. CTA tile (GM*WM) x (GN*WN). 8 warps. K = (KT-1)*64 + kklast*16.
// OT=0: raw f16 store. OT=1: merged-scores epilogue. OT=2: normalize + fused logits.
template<int OT, int WM, int WN, int GM, int GN, int STAGES>
__global__ __launch_bounds__(256, 2) void k_gemmh(
    const __half* __restrict__ A, int lda, int amod, size_t sA,
    const __half* __restrict__ B, int ldb, size_t sB,
    void* __restrict__ Cv, int ldc, size_t sC, int KT, int kklast,
    const __half* __restrict__ qv, float* __restrict__ out, float* __restrict__ rsum)
{
    constexpr int BM  = GM*WM;
    constexpr int BN  = GN*WN;
    constexpr int ASZ = BM*128;
    constexpr int BSZ = BN*128;
    constexpr int STG = ASZ + BSZ;
    extern __shared__ char smem[];
    const int tid = threadIdx.x, wid = tid>>5, lane = tid&31;
    const int wm = wid % GM, wn = wid / GM;
    const int z = blockIdx.z;
    A += (size_t)(amod ? (z % amod) : z) * sA;
    B += (size_t)z * sB;
    const int m0 = blockIdx.y*BM, n0 = blockIdx.x*BN;
    const uint32_t sbase = smem_u32(smem);
    const int lrow = tid >> 3, lch = tid & 7;

    uint32_t acc[WM/16][WN/8][2];
    #pragma unroll
    for (int i=0;i<WM/16;i++)
        #pragma unroll
        for (int j=0;j<WN/8;j++){ acc[i][j][0]=0u; acc[i][j][1]=0u; }

    auto load_tile = [&](int kt, int buf){
        const __half* Ab = A + (size_t)m0*lda + kt*64;
        const __half* Bb = B + (size_t)n0*ldb + kt*64;
        uint32_t da = sbase + buf*STG;
        uint32_t db = da + ASZ;
        #pragma unroll
        for (int c = 0; c < BM/32; c++){
            int row = lrow + c*32;
            cpa16(da + SW128(row*128 + lch*16), Ab + (size_t)row*lda + lch*8);
        }
        #pragma unroll
        for (int c = 0; c < BN/32; c++){
            int row = lrow + c*32;
            cpa16(db + SW128(row*128 + lch*16), Bb + (size_t)row*ldb + lch*8);
        }
        asm volatile("cp.async.commit_group;");
    };

    #pragma unroll
    for (int s = 0; s < STAGES-1; s++) load_tile(s, s);

    for (int kt = 0; kt < KT; kt++){
        if (kt + STAGES-1 < KT) load_tile(kt + STAGES-1, (kt + STAGES-1) % STAGES);
        if (kt + 1 >= KT)      asm volatile("cp.async.wait_group 0;");
        else if (STAGES == 2 || kt + 2 >= KT) asm volatile("cp.async.wait_group 1;");
        else                   asm volatile("cp.async.wait_group 2;");
        __syncthreads();
        const uint32_t sA_ = sbase + (kt % STAGES)*STG;
        const uint32_t sB_ = sA_ + ASZ;
        const int kkmax = (kt == KT-1) ? kklast : 4;
        #pragma unroll
        for (int kk = 0; kk < 4; kk++){
            if (kk >= kkmax) break;
            const int colb = kk*32 + ((lane >> 4) << 4);
            uint32_t a[WM/16][4], b[WN/16][4];
            #pragma unroll
            for (int i = 0; i < WM/16; i++)
                ldm4(a[i], sA_ + SW128((wm*WM + i*16 + (lane & 15))*128 + colb));
            #pragma unroll
            for (int j = 0; j < WN/16; j++)
                ldm4(b[j], sB_ + SW128((wn*WN + j*16 + (lane & 15))*128 + colb));
            #pragma unroll
            for (int i = 0; i < WM/16; i++)
                #pragma unroll
                for (int jj = 0; jj < WN/8; jj++)
                    mma16816h(acc[i][jj], a[i], b[jj>>1][jj&1], b[jj>>1][2+(jj&1)]);
        }
        __syncthreads();
    }

    if (OT == 0) {
        __half* C = (__half*)Cv + (size_t)z * sC;
        #pragma unroll
        for (int i = 0; i < WM/16; i++){
            int r0 = m0 + wm*WM + i*16 + (lane >> 2);
            #pragma unroll
            for (int jj = 0; jj < WN/8; jj++){
                int cc = n0 + wn*WN + jj*8 + (lane & 3)*2;
                *(uint32_t*)(C + (size_t)r0*ldc + cc)     = acc[i][jj][0];
                *(uint32_t*)(C + (size_t)(r0+8)*ldc + cc) = acc[i][jj][1];
            }
        }
    } else if (OT == 1) {
        const int h = z;
        const uint32_t L2E = 0x3dc53dc5u;  // half2(1.4427)
        const int wA = n0 / SKCOL;
        const int bnd = (wA + 1) * SKCOL;
        float rsA[WM/16][2], rsB[WM/16][2];
        #pragma unroll
        for (int i=0;i<WM/16;i++){ rsA[i][0]=0.f; rsA[i][1]=0.f; rsB[i][0]=0.f; rsB[i][1]=0.f; }
        #pragma unroll
        for (int i = 0; i < WM/16; i++){
            int r0 = m0 + wm*WM + i*16 + (lane >> 2);
            #pragma unroll
            for (int jj = 0; jj < WN/8; jj++){
                int cc = n0 + wn*WN + jj*8 + (lane & 3)*2;
                if (cc < NMRG) {
                    int hiw = (cc >= bnd);
                    int w = wA + hiw;
                    int lc = cc - w*SKCOL;
                    __half* C = g_attn[w*2 + h];
                    __half2 m0h = __hmul2(*(__half2*)&acc[i][jj][0], *(__half2*)&L2E);
                    __half2 m1h = __hmul2(*(__half2*)&acc[i][jj][1], *(__half2*)&L2E);
                    uint32_t e0 = h2ex2(*(uint32_t*)&m0h);
                    uint32_t e1 = h2ex2(*(uint32_t*)&m1h);
                    *(uint32_t*)(C + (size_t)r0*KPAD + lc)     = e0;
                    *(uint32_t*)(C + (size_t)(r0+8)*KPAD + lc) = e1;
                    float2 f0 = __half22float2(*(__half2*)&e0);
                    float2 f1 = __half22float2(*(__half2*)&e1);
                    if (hiw) { rsB[i][0] += f0.x + f0.y; rsB[i][1] += f1.x + f1.y; }
                    else     { rsA[i][0] += f0.x + f0.y; rsA[i][1] += f1.x + f1.y; }
                }
            }
        }
        #pragma unroll
        for (int i = 0; i < WM/16; i++){
            int r0 = m0 + wm*WM + i*16 + (lane >> 2);
            #pragma unroll
            for (int rr = 0; rr < 2; rr++){
                float sa = rsA[i][rr], sb = rsB[i][rr];
                sa += __shfl_xor_sync(0xffffffffu, sa, 1);
                sa += __shfl_xor_sync(0xffffffffu, sa, 2);
                sb += __shfl_xor_sync(0xffffffffu, sb, 1);
                sb += __shfl_xor_sync(0xffffffffu, sb, 2);
                if ((lane & 3) == 0) {
                    int row = r0 + rr*8;
                    if (sa != 0.f) atomicAdd(&g_rowsum[wA*2 + h][row], sa);
                    if (sb != 0.f) atomicAdd(&g_rowsum[(wA+1)*2 + h][row], sb);
                }
            }
        }
    } else {
        const int w = z >> 1, h = z & 1;
        const int q0 = m0 / NTUP;
        const int qb = (q0 + 1) * NTUP;
        const float* rz = rsum + (size_t)z * MPAD;
        float s0 = 0.f, s1 = 0.f;
        #pragma unroll
        for (int i = 0; i < WM/16; i++){
            int rb = m0 + wm*WM + i*16 + (lane >> 2);
            #pragma unroll
            for (int rr = 0; rr < 2; rr++){
                int row = rb + rr*8;
                if (row < KROWS) {
                    const float inv = 1.f / rz[row];
                    const __half* qrow = qv + (size_t)row*DIM + h*DH;
                    float part = 0.f;
                    #pragma unroll
                    for (int jj = 0; jj < WN/8; jj++){
                        int cc = n0 + wn*WN + jj*8 + (lane & 3)*2;
                        float2 v = __half22float2(*(__half2*)&acc[i][jj][rr]);
                        float2 q2 = __half22float2(*(const __half2*)(qrow + cc));
                        float d0 = q2.x - v.x*inv;
                        float d1 = q2.y - v.y*inv;
                        part += d0*d0 + d1*d1;
                    }
                    if (row >= qb) s1 += part; else s0 += part;
                }
            }
        }
        float* red = (float*)smem;
        red[tid] = s0; red[256 + tid] = s1;
        __syncthreads();
        #pragma unroll
        for (int st = 128; st > 0; st >>= 1){
            if (tid < st) { red[tid] += red[tid+st]; red[256+tid] += red[256+tid+st]; }
            __syncthreads();
        }
        if (tid == 0 && red[0]   != 0.f) atomicAdd(&out[q0*WAY + w], -red[0]   * (1.f/NTUP));
        if (tid == 1 && q0 + 1 < NQ && red[256] != 0.f)
            atomicAdd(&out[(q0+1)*WAY + w], -red[256] * (1.f/NTUP));
    }
}

// ---------------- tuple combine + bias + LayerNorm (coalesced outputs) ----------------
__global__ __launch_bounds__(192) void k_combine(
    const float* __restrict__ kb, const float* __restrict__ vb,
    const float* __restrict__ lg, const float* __restrict__ lb)
{
    const int bid = blockIdx.x;
    const int v = bid / NTUP, t = bid % NTUP;
    const int tid = threadIdx.x, lane = tid & 31, wrp = tid >> 5;
    __shared__ float redS[6], redQ[6];
    __shared__ int fr[3];
    if (tid < 3) fr[tid] = g_tuples[t*3 + tid];
    __syncthreads();

    const __half2* Pb[3];
    #pragma unroll
    for (int j = 0; j < 3; j++)
        Pb[j] = (const __half2*)(g_P + (size_t)(v*SEQ + fr[j])*6912) + j*1152;

    float2 kv[3], vv[3];
    float lsum = 0.f, lsq = 0.f;
    #pragma unroll
    for (int ii = 0; ii < 3; ii++) {
        int i = tid + ii*192;
        int d0 = 2*i;
        float2 ka = *(const float2*)(kb + d0);
        float2 va = *(const float2*)(vb + d0);
        #pragma unroll
        for (int j = 0; j < 3; j++) {
            float2 pk = __half22float2(Pb[j][i]);
            float2 pv = __half22float2(Pb[j][576 + i]);
            ka.x += pk.x; ka.y += pk.y;
            va.x += pv.x; va.y += pv.y;
        }
        kv[ii] = ka; vv[ii] = va;
        lsum += ka.x + ka.y;
        lsq  += ka.x*ka.x + ka.y*ka.y;
    }
    #pragma unroll
    for (int o = 16; o; o >>= 1) {
        lsum += __shfl_xor_sync(0xffffffffu, lsum, o);
        lsq  += __shfl_xor_sync(0xffffffffu, lsq,  o);
    }
    if (lane == 0) { redS[wrp] = lsum; redQ[wrp] = lsq; }
    __syncthreads();
    if (tid == 0) {
        float s = 0.f, q = 0.f;
        #pragma unroll
        for (int wv = 0; wv < 6; wv++) { s += redS[wv]; q += redQ[wv]; }
        redS[0] = s; redQ[0] = q;
    }
    __syncthreads();
    float mu = redS[0] * (1.f/1152.f);
    float var = redQ[0] * (1.f/1152.f) - mu*mu;
    float rstd = rsqrtf(var + 1e-5f);

    int w = 0, s = 0;
    if (v < NS) { w = v / SHOT; s = v % SHOT; }
    #pragma unroll
    for (int ii = 0; ii < 3; ii++) {
        int i = tid + ii*192;
        int d0 = 2*i;
        int h = (d0 >= DH) ? 1 : 0;
        int dd = d0 - h*DH;
        float2 g = *(const float2*)(lg + d0);
        float2 b = *(const float2*)(lb + d0);
        float ox = ((kv[ii].x - mu)*rstd*g.x + b.x) * RS24;
        float oy = ((kv[ii].y - mu)*rstd*g.y + b.y) * RS24;
        __half2 oh = __floats2half2_rn(ox, oy);
        __half2 vh = __floats2half2_rn(vv[ii].x, vv[ii].y);
        if (v < NS) {
            int row = s*NTUP + t;
            *(__half2*)&g_skzm[h][(size_t)(w*SKCOL + row)*DH + dd] = oh;
            *(__half2*)&g_sv[w*2 + h][(size_t)row*DH + dd] = vh;
        } else {
            *(__half2*)&g_qk[h][(size_t)((v-NS)*NTUP + t)*DH + dd] = oh;
            *(__half2*)&g_qv[(size_t)((v-NS)*NTUP + t)*DIM + d0] = vh;
        }
    }
}

// ---------------- launch ----------------
extern "C" void kernel_launch(void* const* d_in, const int* in_sizes, int n_in,
                              void* d_out, int out_size)
{
    const float* support = (const float*)d_in[0];
    const float* queries = (const float*)d_in[1];
    const float* k_w  = (const float*)d_in[3];
    const float* k_b  = (const float*)d_in[4];
    const float* v_w  = (const float*)d_in[5];
    const float* v_b  = (const float*)d_in[6];
    const float* ln_g = (const float*)d_in[7];
    const float* ln_b = (const float*)d_in[8];
    float* out = (float*)d_out;

    void *pAp, *pWT, *pP, *pQK, *pSKZM, *pSVT, *pATT, *pQV, *pRS;
    cudaGetSymbolAddress(&pAp,   g_Ap);
    cudaGetSymbolAddress(&pWT,   g_wT);
    cudaGetSymbolAddress(&pP,    g_P);
    cudaGetSymbolAddress(&pQK,   g_qk);
    cudaGetSymbolAddress(&pSKZM, g_skzm);
    cudaGetSymbolAddress(&pSVT,  g_svT);
    cudaGetSymbolAddress(&pATT,  g_attn);
    cudaGetSymbolAddress(&pQV,   g_qv);
    cudaGetSymbolAddress(&pRS,   g_rowsum);

    auto gemm_pp = k_gemmh<0,32,32,2,4,3>;   // proj, 64x128 tiles
    auto gemm_sc = k_gemmh<1,32,64,4,2,3>;   // merged scores, 128x128 tiles
    auto gemm_pr = k_gemmh<2,64,48,2,4,2>;   // proto, 128x192 tiles (R13 config)
    cudaFuncSetAttribute(gemm_pp, cudaFuncAttributeMaxDynamicSharedMemorySize, 3*24576);
    cudaFuncSetAttribute(gemm_sc, cudaFuncAttributeMaxDynamicSharedMemorySize, 3*32768);
    cudaFuncSetAttribute(gemm_pr, cudaFuncAttributeMaxDynamicSharedMemorySize, 2*40960);

    // fork/join side stream (capture-legal; proven R8/R10/R12/R13)
    cudaStream_t s1;
    cudaStreamCreateWithFlags(&s1, cudaStreamNonBlocking);
    cudaEvent_t e0, eA, eC, eT;
    cudaEventCreateWithFlags(&e0, cudaEventDisableTiming);
    cudaEventCreateWithFlags(&eA, cudaEventDisableTiming);
    cudaEventCreateWithFlags(&eC, cudaEventDisableTiming);
    cudaEventCreateWithFlags(&eT, cudaEventDisableTiming);

    k_init<<<432, 256>>>(out);
    cudaEventRecord(e0, 0);

    // side stream: A-prep (overlaps transW on main)
    cudaStreamWaitEvent(s1, e0, 0);
    k_prepA<<<NV*SEQ, 128, 0, s1>>>(support, queries);
    cudaEventRecord(eA, s1);

    k_transW<<<dim3(36, 36, 6), 256>>>(k_w, v_w);
    cudaStreamWaitEvent(0, eA, 0);

    // proj: P[960(900), 6912] = Ap @ wT^T, K=1152
    gemm_pp<<<dim3(54, 15, 1), 256, 3*24576>>>(
        (const __half*)pAp, DIM, 1, 0,
        (const __half*)pWT, DIM, 0,
        pP, 6912, 0, 18, 4, nullptr, nullptr, nullptr);

    k_combine<<<NV*NTUP, 192>>>(k_b, v_b, ln_g, ln_b);
    cudaEventRecord(eC, 0);

    // V transpose on side stream, overlapping the scores GEMM
    cudaStreamWaitEvent(s1, eC, 0);
    k_transV<<<dim3(18, 9, WAY*HH), 256, 0, s1>>>();
    cudaEventRecord(eT, s1);

    // merged scores: per h: exp(qk[h] @ skzm[h]^T) -> per-(w,h) attn + rowsum, K=576 exact
    gemm_sc<<<dim3(NMRGP/128, MPAD/128, HH), 256, 3*32768>>>(
        (const __half*)pQK, DH, 2, (size_t)MPAD*DH,
        (const __half*)pSKZM, DH, (size_t)NMRGP*DH,
        nullptr, 0, 0, 9, 4, nullptr, nullptr, nullptr);

    // proto + normalize + fused logits: K = 17*64 + 1*16 = 1104 >= 1100 (cols 1100-1103 zero)
    cudaStreamWaitEvent(0, eT, 0);
    gemm_pr<<<dim3(3, 86, WAY*HH), 256, 2*40960>>>(
        (const __half*)pATT, KPAD, 0, (size_t)MPAD*KPAD,
        (const __half*)pSVT, KPAD, (size_t)DH*KPAD,
        nullptr, 0, 0, 18, 1, (const __half*)pQV, out, (float*)pRS);
}

// round 16
// speedup vs baseline: 1.0979x; 1.0308x over previous
#include <cuda_runtime.h>
#include <cuda_fp16.h>
#include <math.h>
#include <stdint.h>

#define NS 25
#define NQ 50
#define NV 75
#define SEQ 12
#define DIM 1152
#define HH 2
#define DH 576
#define NTUP 220
#define WAY 5
#define SHOT 5
#define KROWS (NQ*NTUP)      /* 11000 */
#define MPAD  11008
#define SKCOL (SHOT*NTUP)    /* 1100 per way */
#define NMRG  5500
#define NMRGP 5504
#define KPAD  1152
#define RS24  0.20412414523193154f

// ---------------- device scratch (zero-initialized; pads stay zero) ----------------
__device__ float g_pe[SEQ*DIM];
__device__ int   g_tuples[NTUP*3];
__device__ __align__(16) __half g_Ap[1024*DIM];
__device__ __align__(16) __half g_wT[6912*DIM];
__device__ __align__(16) __half g_P[(size_t)1024*6912];
__device__ __align__(16) __half g_qk[HH][(size_t)MPAD*DH];
__device__ __align__(16) __half g_skzm[HH][(size_t)NMRGP*DH];
__device__ __align__(16) __half g_sv[WAY*HH][(size_t)KPAD*DH];
__device__ __align__(16) __half g_svT[WAY*HH][(size_t)DH*KPAD];
__device__ __align__(16) __half g_qv[(size_t)KROWS*DIM];
__device__ __align__(16) __half g_attn[WAY*HH][(size_t)MPAD*KPAD];
__device__ float g_rowsum[WAY*HH][MPAD];

// ---------------- helpers ----------------
__device__ __forceinline__ uint32_t smem_u32(const void* p){
    uint32_t a;
    asm("{ .reg .u64 t; cvta.to.shared.u64 t, %1; cvt.u32.u64 %0, t; }" : "=r"(a) : "l"(p));
    return a;
}
#define SW128(x) ((x) ^ (((x)>>3)&0x70))

__device__ __forceinline__ void ldm4(uint32_t* r, uint32_t addr){
    asm volatile("ldmatrix.sync.aligned.m8n8.x4.shared.b16 {%0,%1,%2,%3}, [%4];"
        : "=r"(r[0]), "=r"(r[1]), "=r"(r[2]), "=r"(r[3]) : "r"(addr));
}
__device__ __forceinline__ void mma16816h(uint32_t* c, const uint32_t* a, uint32_t b0, uint32_t b1){
    asm volatile("mma.sync.aligned.m16n8k16.row.col.f16.f16.f16.f16 "
        "{%0,%1}, {%2,%3,%4,%5}, {%6,%7}, {%0,%1};"
        : "+r"(c[0]), "+r"(c[1])
        : "r"(a[0]), "r"(a[1]), "r"(a[2]), "r"(a[3]), "r"(b0), "r"(b1));
}
__device__ __forceinline__ void cpa16(uint32_t dst, const void* src){
    asm volatile("cp.async.cg.shared.global [%0], [%1], 16;" :: "r"(dst), "l"(src));
}
__device__ __forceinline__ uint32_t h2ex2(uint32_t h){
    uint32_t o;
    asm("ex2.approx.f16x2 %0, %1;" : "=r"(o) : "r"(h));
    return o;
}

// ---------------- init ----------------
__global__ void k_init(float* out) {
    int gi = blockIdx.x*256 + threadIdx.x;
    if (gi < WAY*HH*MPAD) ((float*)g_rowsum)[gi] = 0.f;
    if (blockIdx.x == 0) {
        int tid = threadIdx.x;
        for (int i = tid; i < SEQ*576; i += 256) {
            int p = i / 576, j = i % 576;
            double dv = exp(-(double)(2*j) * (log(10000.0) / 1152.0));
            double ang = (double)p * dv;
            g_pe[p*DIM + 2*j]     = (float)(sin(ang) * 0.1);
            g_pe[p*DIM + 2*j + 1] = (float)(cos(ang) * 0.1);
        }
        if (tid < NQ*WAY) out[tid] = 0.f;
        if (tid == 0) {
            int idx = 0;
            for (int a = 0; a < SEQ; a++)
                for (int b = a+1; b < SEQ; b++)
                    for (int c = b+1; c < SEQ; c++) {
                        g_tuples[idx*3+0]=a; g_tuples[idx*3+1]=b; g_tuples[idx*3+2]=c; idx++;
                    }
        }
    }
}

__global__ __launch_bounds__(128) void k_prepA(const float* __restrict__ sup,
                                               const float* __restrict__ qry){
    int m = blockIdx.x; int v = m/SEQ, f = m%SEQ;
    const float* src = (v < NS) ? sup + (size_t)m*DIM
                                : qry + ((size_t)(v-NS)*SEQ + f)*DIM;
    for (int i = threadIdx.x; i < DIM; i += 128)
        g_Ap[(size_t)m*DIM + i] = __float2half(src[i] + g_pe[f*DIM + i]);
}

__global__ __launch_bounds__(256) void k_transW(const float* __restrict__ kw,
                                                const float* __restrict__ vw){
    __shared__ float t[32][33];
    int z = blockIdx.z; int j = z>>1, which = z&1;
    const float* W = which ? vw : kw;
    int o0 = blockIdx.x*32, k0 = blockIdx.y*32;
    int tx = threadIdx.x & 31, ty = threadIdx.x >> 5;
    #pragma unroll
    for (int r = 0; r < 4; r++)
        t[ty + r*8][tx] = W[(size_t)(j*1152 + k0 + ty + r*8)*1152 + o0 + tx];
    __syncthreads();
    #pragma unroll
    for (int r = 0; r < 4; r++)
        g_wT[(size_t)(j*2304 + which*1152 + o0 + ty + r*8)*1152 + k0 + tx]
            = __float2half(t[tx][ty + r*8]);
}

// ---------------- V transpose: sv[z][1152p x 576] -> svT[z][576 x 1152] ----------------
__global__ __launch_bounds__(256) void k_transV(){
    __shared__ __half t[64][65];
    const int z = blockIdx.z;
    const int r0 = blockIdx.x * 64;
    const int c0 = blockIdx.y * 64;
    const int tx = threadIdx.x & 31, ty = threadIdx.x >> 5;
    const __half* sv = g_sv[z];
    __half* svT = g_svT[z];
    #pragma unroll
    for (int r = 0; r < 8; r++){
        int row = ty + r*8;
        __half2 v = *(const __half2*)(sv + (size_t)(r0 + row)*DH + c0 + tx*2);
        t[row][tx*2]   = __low2half(v);
        t[row][tx*2+1] = __high2half(v);
    }
    __syncthreads();
    #pragma unroll
    for (int c = 0; c < 8; c++){
        int col = ty + c*8;
        __half2 v = __halves2half2(t[tx*2][col], t[tx*2+1][col]);
        *(__half2*)(svT + (size_t)(c0 + col)*KPAD + r0 + tx*2) = v;
    }
}

// ---------------- f16 NT GEMM, f16 acc, pipelined cp.async ----------------
// C[M,N] = A[M,K] @ B[N,K]^T. CTA tile (GM*WM) x (GN*WN). 8 warps.
// K = (KT-1)*64 + KKL*16 (KKL compile-time; KKL=4 => no branch at all).
// OT=0: raw f16 store. OT=1: merged-scores epilogue. OT=2: normalize + fused logits.
template<int OT, int WM, int WN, int GM, int GN, int STAGES, int KKL>
__global__ __launch_bounds__(256, 2) void k_gemmh(
    const __half* __restrict__ A, int lda, int amod, size_t sA,
    const __half* __restrict__ B, int ldb, size_t sB,
    void* __restrict__ Cv, int ldc, size_t sC, int KT,
    const __half* __restrict__ qv, float* __restrict__ out, float* __restrict__ rsum)
{
    constexpr int BM  = GM*WM;
    constexpr int BN  = GN*WN;
    constexpr int ASZ = BM*128;
    constexpr int BSZ = BN*128;
    constexpr int STG = ASZ + BSZ;
    extern __shared__ char smem[];
    const int tid = threadIdx.x, wid = tid>>5, lane = tid&31;
    const int wm = wid % GM, wn = wid / GM;
    const int z = blockIdx.z;
    A += (size_t)(amod ? (z % amod) : z) * sA;
    B += (size_t)z * sB;
    const int m0 = blockIdx.y*BM, n0 = blockIdx.x*BN;
    const uint32_t sbase = smem_u32(smem);
    const int lrow = tid >> 3, lch = tid & 7;

    uint32_t acc[WM/16][WN/8][2];
    #pragma unroll
    for (int i=0;i<WM/16;i++)
        #pragma unroll
        for (int j=0;j<WN/8;j++){ acc[i][j][0]=0u; acc[i][j][1]=0u; }

    auto load_tile = [&](int kt, int buf){
        const __half* Ab = A + (size_t)m0*lda + kt*64;
        const __half* Bb = B + (size_t)n0*ldb + kt*64;
        uint32_t da = sbase + buf*STG;
        uint32_t db = da + ASZ;
        #pragma unroll
        for (int c = 0; c < BM/32; c++){
            int row = lrow + c*32;
            cpa16(da + SW128(row*128 + lch*16), Ab + (size_t)row*lda + lch*8);
        }
        #pragma unroll
        for (int c = 0; c < BN/32; c++){
            int row = lrow + c*32;
            cpa16(db + SW128(row*128 + lch*16), Bb + (size_t)row*ldb + lch*8);
        }
        asm volatile("cp.async.commit_group;");
    };

    // one kk step (constant kk), shared by both unrolled bodies
    auto kk_step = [&](uint32_t sA_, uint32_t sB_, int kk){
        const int colb = kk*32 + ((lane >> 4) << 4);
        uint32_t a[WM/16][4], b[WN/16][4];
        #pragma unroll
        for (int i = 0; i < WM/16; i++)
            ldm4(a[i], sA_ + SW128((wm*WM + i*16 + (lane & 15))*128 + colb));
        #pragma unroll
        for (int j = 0; j < WN/16; j++)
            ldm4(b[j], sB_ + SW128((wn*WN + j*16 + (lane & 15))*128 + colb));
        #pragma unroll
        for (int i = 0; i < WM/16; i++)
            #pragma unroll
            for (int jj = 0; jj < WN/8; jj++)
                mma16816h(acc[i][jj], a[i], b[jj>>1][jj&1], b[jj>>1][2+(jj&1)]);
    };

    #pragma unroll
    for (int s = 0; s < STAGES-1; s++) load_tile(s, s);

    for (int kt = 0; kt < KT; kt++){
        if (kt + STAGES-1 < KT) load_tile(kt + STAGES-1, (kt + STAGES-1) % STAGES);
        if (kt + 1 >= KT)      asm volatile("cp.async.wait_group 0;");
        else if (STAGES == 2 || kt + 2 >= KT) asm volatile("cp.async.wait_group 1;");
        else                   asm volatile("cp.async.wait_group 2;");
        __syncthreads();
        const uint32_t sA_ = sbase + (kt % STAGES)*STG;
        const uint32_t sB_ = sA_ + ASZ;
        if (KKL == 4 || kt < KT-1) {
            #pragma unroll
            for (int kk = 0; kk < 4; kk++) kk_step(sA_, sB_, kk);
        } else {
            #pragma unroll
            for (int kk = 0; kk < KKL; kk++) kk_step(sA_, sB_, kk);
        }
        __syncthreads();
    }

    if (OT == 0) {
        __half* C = (__half*)Cv + (size_t)z * sC;
        #pragma unroll
        for (int i = 0; i < WM/16; i++){
            int r0 = m0 + wm*WM + i*16 + (lane >> 2);
            #pragma unroll
            for (int jj = 0; jj < WN/8; jj++){
                int cc = n0 + wn*WN + jj*8 + (lane & 3)*2;
                *(uint32_t*)(C + (size_t)r0*ldc + cc)     = acc[i][jj][0];
                *(uint32_t*)(C + (size_t)(r0+8)*ldc + cc) = acc[i][jj][1];
            }
        }
    } else if (OT == 1) {
        const int h = z;
        const uint32_t L2E = 0x3dc53dc5u;  // half2(1.4427)
        const int wA = n0 / SKCOL;
        const int bnd = (wA + 1) * SKCOL;
        float rsA[WM/16][2], rsB[WM/16][2];
        #pragma unroll
        for (int i=0;i<WM/16;i++){ rsA[i][0]=0.f; rsA[i][1]=0.f; rsB[i][0]=0.f; rsB[i][1]=0.f; }
        #pragma unroll
        for (int i = 0; i < WM/16; i++){
            int r0 = m0 + wm*WM + i*16 + (lane >> 2);
            #pragma unroll
            for (int jj = 0; jj < WN/8; jj++){
                int cc = n0 + wn*WN + jj*8 + (lane & 3)*2;
                if (cc < NMRG) {
                    int hiw = (cc >= bnd);
                    int w = wA + hiw;
                    int lc = cc - w*SKCOL;
                    __half* C = g_attn[w*2 + h];
                    __half2 m0h = __hmul2(*(__half2*)&acc[i][jj][0], *(__half2*)&L2E);
                    __half2 m1h = __hmul2(*(__half2*)&acc[i][jj][1], *(__half2*)&L2E);
                    uint32_t e0 = h2ex2(*(uint32_t*)&m0h);
                    uint32_t e1 = h2ex2(*(uint32_t*)&m1h);
                    *(uint32_t*)(C + (size_t)r0*KPAD + lc)     = e0;
                    *(uint32_t*)(C + (size_t)(r0+8)*KPAD + lc) = e1;
                    float2 f0 = __half22float2(*(__half2*)&e0);
                    float2 f1 = __half22float2(*(__half2*)&e1);
                    if (hiw) { rsB[i][0] += f0.x + f0.y; rsB[i][1] += f1.x + f1.y; }
                    else     { rsA[i][0] += f0.x + f0.y; rsA[i][1] += f1.x + f1.y; }
                }
            }
        }
        #pragma unroll
        for (int i = 0; i < WM/16; i++){
            int r0 = m0 + wm*WM + i*16 + (lane >> 2);
            #pragma unroll
            for (int rr = 0; rr < 2; rr++){
                float sa = rsA[i][rr], sb = rsB[i][rr];
                sa += __shfl_xor_sync(0xffffffffu, sa, 1);
                sa += __shfl_xor_sync(0xffffffffu, sa, 2);
                sb += __shfl_xor_sync(0xffffffffu, sb, 1);
                sb += __shfl_xor_sync(0xffffffffu, sb, 2);
                if ((lane & 3) == 0) {
                    int row = r0 + rr*8;
                    if (sa != 0.f) atomicAdd(&g_rowsum[wA*2 + h][row], sa);
                    if (sb != 0.f) atomicAdd(&g_rowsum[(wA+1)*2 + h][row], sb);
                }
            }
        }
    } else {
        const int w = z >> 1, h = z & 1;
        const int q0 = m0 / NTUP;
        const int qb = (q0 + 1) * NTUP;
        const float* rz = rsum + (size_t)z * MPAD;
        float s0 = 0.f, s1 = 0.f;
        #pragma unroll
        for (int i = 0; i < WM/16; i++){
            int rb = m0 + wm*WM + i*16 + (lane >> 2);
            #pragma unroll
            for (int rr = 0; rr < 2; rr++){
                int row = rb + rr*8;
                if (row < KROWS) {
                    const float inv = 1.f / rz[row];
                    const __half* qrow = qv + (size_t)row*DIM + h*DH;
                    float part = 0.f;
                    #pragma unroll
                    for (int jj = 0; jj < WN/8; jj++){
                        int cc = n0 + wn*WN + jj*8 + (lane & 3)*2;
                        float2 v = __half22float2(*(__half2*)&acc[i][jj][rr]);
                        float2 q2 = __half22float2(*(const __half2*)(qrow + cc));
                        float d0 = q2.x - v.x*inv;
                        float d1 = q2.y - v.y*inv;
                        part += d0*d0 + d1*d1;
                    }
                    if (row >= qb) s1 += part; else s0 += part;
                }
            }
        }
        float* red = (float*)smem;
        red[tid] = s0; red[256 + tid] = s1;
        __syncthreads();
        #pragma unroll
        for (int st = 128; st > 0; st >>= 1){
            if (tid < st) { red[tid] += red[tid+st]; red[256+tid] += red[256+tid+st]; }
            __syncthreads();
        }
        if (tid == 0 && red[0]   != 0.f) atomicAdd(&out[q0*WAY + w], -red[0]   * (1.f/NTUP));
        if (tid == 1 && q0 + 1 < NQ && red[256] != 0.f)
            atomicAdd(&out[(q0+1)*WAY + w], -red[256] * (1.f/NTUP));
    }
}

// ---------------- tuple combine + bias + LayerNorm (coalesced outputs) ----------------
__global__ __launch_bounds__(192) void k_combine(
    const float* __restrict__ kb, const float* __restrict__ vb,
    const float* __restrict__ lg, const float* __restrict__ lb)
{
    const int bid = blockIdx.x;
    const int v = bid / NTUP, t = bid % NTUP;
    const int tid = threadIdx.x, lane = tid & 31, wrp = tid >> 5;
    __shared__ float redS[6], redQ[6];
    __shared__ int fr[3];
    if (tid < 3) fr[tid] = g_tuples[t*3 + tid];
    __syncthreads();

    const __half2* Pb[3];
    #pragma unroll
    for (int j = 0; j < 3; j++)
        Pb[j] = (const __half2*)(g_P + (size_t)(v*SEQ + fr[j])*6912) + j*1152;

    float2 kv[3], vv[3];
    float lsum = 0.f, lsq = 0.f;
    #pragma unroll
    for (int ii = 0; ii < 3; ii++) {
        int i = tid + ii*192;
        int d0 = 2*i;
        float2 ka = *(const float2*)(kb + d0);
        float2 va = *(const float2*)(vb + d0);
        #pragma unroll
        for (int j = 0; j < 3; j++) {
            float2 pk = __half22float2(Pb[j][i]);
            float2 pv = __half22float2(Pb[j][576 + i]);
            ka.x += pk.x; ka.y += pk.y;
            va.x += pv.x; va.y += pv.y;
        }
        kv[ii] = ka; vv[ii] = va;
        lsum += ka.x + ka.y;
        lsq  += ka.x*ka.x + ka.y*ka.y;
    }
    #pragma unroll
    for (int o = 16; o; o >>= 1) {
        lsum += __shfl_xor_sync(0xffffffffu, lsum, o);
        lsq  += __shfl_xor_sync(0xffffffffu, lsq,  o);
    }
    if (lane == 0) { redS[wrp] = lsum; redQ[wrp] = lsq; }
    __syncthreads();
    if (tid == 0) {
        float s = 0.f, q = 0.f;
        #pragma unroll
        for (int wv = 0; wv < 6; wv++) { s += redS[wv]; q += redQ[wv]; }
        redS[0] = s; redQ[0] = q;
    }
    __syncthreads();
    float mu = redS[0] * (1.f/1152.f);
    float var = redQ[0] * (1.f/1152.f) - mu*mu;
    float rstd = rsqrtf(var + 1e-5f);

    int w = 0, s = 0;
    if (v < NS) { w = v / SHOT; s = v % SHOT; }
    #pragma unroll
    for (int ii = 0; ii < 3; ii++) {
        int i = tid + ii*192;
        int d0 = 2*i;
        int h = (d0 >= DH) ? 1 : 0;
        int dd = d0 - h*DH;
        float2 g = *(const float2*)(lg + d0);
        float2 b = *(const float2*)(lb + d0);
        float ox = ((kv[ii].x - mu)*rstd*g.x + b.x) * RS24;
        float oy = ((kv[ii].y - mu)*rstd*g.y + b.y) * RS24;
        __half2 oh = __floats2half2_rn(ox, oy);
        __half2 vh = __floats2half2_rn(vv[ii].x, vv[ii].y);
        if (v < NS) {
            int row = s*NTUP + t;
            *(__half2*)&g_skzm[h][(size_t)(w*SKCOL + row)*DH + dd] = oh;
            *(__half2*)&g_sv[w*2 + h][(size_t)row*DH + dd] = vh;
        } else {
            *(__half2*)&g_qk[h][(size_t)((v-NS)*NTUP + t)*DH + dd] = oh;
            *(__half2*)&g_qv[(size_t)((v-NS)*NTUP + t)*DIM + d0] = vh;
        }
    }
}

// ---------------- launch ----------------
extern "C" void kernel_launch(void* const* d_in, const int* in_sizes, int n_in,
                              void* d_out, int out_size)
{
    const float* support = (const float*)d_in[0];
    const float* queries = (const float*)d_in[1];
    const float* k_w  = (const float*)d_in[3];
    const float* k_b  = (const float*)d_in[4];
    const float* v_w  = (const float*)d_in[5];
    const float* v_b  = (const float*)d_in[6];
    const float* ln_g = (const float*)d_in[7];
    const float* ln_b = (const float*)d_in[8];
    float* out = (float*)d_out;

    void *pAp, *pWT, *pP, *pQK, *pSKZM, *pSVT, *pATT, *pQV, *pRS;
    cudaGetSymbolAddress(&pAp,   g_Ap);
    cudaGetSymbolAddress(&pWT,   g_wT);
    cudaGetSymbolAddress(&pP,    g_P);
    cudaGetSymbolAddress(&pQK,   g_qk);
    cudaGetSymbolAddress(&pSKZM, g_skzm);
    cudaGetSymbolAddress(&pSVT,  g_svT);
    cudaGetSymbolAddress(&pATT,  g_attn);
    cudaGetSymbolAddress(&pQV,   g_qv);
    cudaGetSymbolAddress(&pRS,   g_rowsum);

    auto gemm_pp = k_gemmh<0,32,32,2,4,3,4>;   // proj, 64x128 tiles, K exact
    auto gemm_sc = k_gemmh<1,32,64,4,2,3,4>;   // merged scores, K exact
    auto gemm_pr = k_gemmh<2,64,48,2,4,2,1>;   // proto, last k-tile = 1 kk (K=1104>=1100)
    cudaFuncSetAttribute(gemm_pp, cudaFuncAttributeMaxDynamicSharedMemorySize, 3*24576);
    cudaFuncSetAttribute(gemm_sc, cudaFuncAttributeMaxDynamicSharedMemorySize, 3*32768);
    cudaFuncSetAttribute(gemm_pr, cudaFuncAttributeMaxDynamicSharedMemorySize, 2*40960);

    // fork/join side stream (capture-legal; proven R8/R10/R12/R13)
    cudaStream_t s1;
    cudaStreamCreateWithFlags(&s1, cudaStreamNonBlocking);
    cudaEvent_t e0, eA, eC, eT;
    cudaEventCreateWithFlags(&e0, cudaEventDisableTiming);
    cudaEventCreateWithFlags(&eA, cudaEventDisableTiming);
    cudaEventCreateWithFlags(&eC, cudaEventDisableTiming);
    cudaEventCreateWithFlags(&eT, cudaEventDisableTiming);

    k_init<<<432, 256>>>(out);
    cudaEventRecord(e0, 0);

    // side stream: A-prep (overlaps transW on main)
    cudaStreamWaitEvent(s1, e0, 0);
    k_prepA<<<NV*SEQ, 128, 0, s1>>>(support, queries);
    cudaEventRecord(eA, s1);

    k_transW<<<dim3(36, 36, 6), 256>>>(k_w, v_w);
    cudaStreamWaitEvent(0, eA, 0);

    // proj: P[960(900), 6912] = Ap @ wT^T, K=1152
    gemm_pp<<<dim3(54, 15, 1), 256, 3*24576>>>(
        (const __half*)pAp, DIM, 1, 0,
        (const __half*)pWT, DIM, 0,
        pP, 6912, 0, 18, nullptr, nullptr, nullptr);

    k_combine<<<NV*NTUP, 192>>>(k_b, v_b, ln_g, ln_b);
    cudaEventRecord(eC, 0);

    // V transpose on side stream, overlapping the scores GEMM
    cudaStreamWaitEvent(s1, eC, 0);
    k_transV<<<dim3(18, 9, WAY*HH), 256, 0, s1>>>();
    cudaEventRecord(eT, s1);

    // merged scores: per h: exp(qk[h] @ skzm[h]^T) -> per-(w,h) attn + rowsum, K=576 exact
    gemm_sc<<<dim3(NMRGP/128, MPAD/128, HH), 256, 3*32768>>>(
        (const __half*)pQK, DH, 2, (size_t)MPAD*DH,
        (const __half*)pSKZM, DH, (size_t)NMRGP*DH,
        nullptr, 0, 0, 9, nullptr, nullptr, nullptr);

    // proto + normalize + fused logits: K = 17*64 + 16 = 1104 >= 1100 (cols 1100-1103 zero)
    cudaStreamWaitEvent(0, eT, 0);
    gemm_pr<<<dim3(3, 86, WAY*HH), 256, 2*40960>>>(
        (const __half*)pATT, KPAD, 0, (size_t)MPAD*KPAD,
        (const __half*)pSVT, KPAD, (size_t)DH*KPAD,
        nullptr, 0, 0, 18, (const __half*)pQV, out, (float*)pRS);
}

// round 17
// speedup vs baseline: 1.1003x; 1.0022x over previous
#include <cuda_runtime.h>
#include <cuda_fp16.h>
#include <math.h>
#include <stdint.h>

#define NS 25
#define NQ 50
#define NV 75
#define SEQ 12
#define DIM 1152
#define HH 2
#define DH 576
#define NTUP 220
#define WAY 5
#define SHOT 5
#define KROWS (NQ*NTUP)      /* 11000 */
#define MPAD  11008
#define SKCOL (SHOT*NTUP)    /* 1100 per way */
#define NMRG  5500
#define NMRGP 5504
#define KPAD  1152
#define RS24  0.20412414523193154f

// ---------------- device scratch (zero-initialized; pads stay zero) ----------------
__device__ float g_pe[SEQ*DIM];
__device__ int   g_tuples[NTUP*3];
__device__ __align__(16) __half g_Ap[1024*DIM];
__device__ __align__(16) __half g_wT[6912*DIM];
__device__ __align__(16) __half g_P[(size_t)1024*6912];
__device__ __align__(16) __half g_qk[HH][(size_t)MPAD*DH];
__device__ __align__(16) __half g_skzm[HH][(size_t)NMRGP*DH];
__device__ __align__(16) __half g_sv[WAY*HH][(size_t)KPAD*DH];
__device__ __align__(16) __half g_svT[WAY*HH][(size_t)DH*KPAD];
__device__ __align__(16) __half g_qv[(size_t)KROWS*DIM];
__device__ __align__(16) __half g_attn[WAY*HH][(size_t)MPAD*KPAD];
__device__ float g_rowsum[WAY*HH][MPAD];

// ---------------- helpers ----------------
__device__ __forceinline__ uint32_t smem_u32(const void* p){
    uint32_t a;
    asm("{ .reg .u64 t; cvta.to.shared.u64 t, %1; cvt.u32.u64 %0, t; }" : "=r"(a) : "l"(p));
    return a;
}
#define SW128(x) ((x) ^ (((x)>>3)&0x70))

__device__ __forceinline__ void ldm4(uint32_t* r, uint32_t addr){
    asm volatile("ldmatrix.sync.aligned.m8n8.x4.shared.b16 {%0,%1,%2,%3}, [%4];"
        : "=r"(r[0]), "=r"(r[1]), "=r"(r[2]), "=r"(r[3]) : "r"(addr));
}
__device__ __forceinline__ void mma16816h(uint32_t* c, const uint32_t* a, uint32_t b0, uint32_t b1){
    asm volatile("mma.sync.aligned.m16n8k16.row.col.f16.f16.f16.f16 "
        "{%0,%1}, {%2,%3,%4,%5}, {%6,%7}, {%0,%1};"
        : "+r"(c[0]), "+r"(c[1])
        : "r"(a[0]), "r"(a[1]), "r"(a[2]), "r"(a[3]), "r"(b0), "r"(b1));
}
__device__ __forceinline__ void cpa16(uint32_t dst, const void* src){
    asm volatile("cp.async.cg.shared.global [%0], [%1], 16;" :: "r"(dst), "l"(src));
}
__device__ __forceinline__ uint32_t h2ex2(uint32_t h){
    uint32_t o;
    asm("ex2.approx.f16x2 %0, %1;" : "=r"(o) : "r"(h));
    return o;
}

// ---------------- init ----------------
__global__ void k_init(float* out) {
    int gi = blockIdx.x*256 + threadIdx.x;
    if (gi < WAY*HH*MPAD) ((float*)g_rowsum)[gi] = 0.f;
    if (blockIdx.x == 0) {
        int tid = threadIdx.x;
        for (int i = tid; i < SEQ*576; i += 256) {
            int p = i / 576, j = i % 576;
            double dv = exp(-(double)(2*j) * (log(10000.0) / 1152.0));
            double ang = (double)p * dv;
            g_pe[p*DIM + 2*j]     = (float)(sin(ang) * 0.1);
            g_pe[p*DIM + 2*j + 1] = (float)(cos(ang) * 0.1);
        }
        if (tid < NQ*WAY) out[tid] = 0.f;
        if (tid == 0) {
            int idx = 0;
            for (int a = 0; a < SEQ; a++)
                for (int b = a+1; b < SEQ; b++)
                    for (int c = b+1; c < SEQ; c++) {
                        g_tuples[idx*3+0]=a; g_tuples[idx*3+1]=b; g_tuples[idx*3+2]=c; idx++;
                    }
        }
    }
}

__global__ __launch_bounds__(128) void k_prepA(const float* __restrict__ sup,
                                               const float* __restrict__ qry){
    int m = blockIdx.x; int v = m/SEQ, f = m%SEQ;
    const float* src = (v < NS) ? sup + (size_t)m*DIM
                                : qry + ((size_t)(v-NS)*SEQ + f)*DIM;
    for (int i = threadIdx.x; i < DIM; i += 128)
        g_Ap[(size_t)m*DIM + i] = __float2half(src[i] + g_pe[f*DIM + i]);
}

__global__ __launch_bounds__(256) void k_transW(const float* __restrict__ kw,
                                                const float* __restrict__ vw){
    __shared__ float t[32][33];
    int z = blockIdx.z; int j = z>>1, which = z&1;
    const float* W = which ? vw : kw;
    int o0 = blockIdx.x*32, k0 = blockIdx.y*32;
    int tx = threadIdx.x & 31, ty = threadIdx.x >> 5;
    #pragma unroll
    for (int r = 0; r < 4; r++)
        t[ty + r*8][tx] = W[(size_t)(j*1152 + k0 + ty + r*8)*1152 + o0 + tx];
    __syncthreads();
    #pragma unroll
    for (int r = 0; r < 4; r++)
        g_wT[(size_t)(j*2304 + which*1152 + o0 + ty + r*8)*1152 + k0 + tx]
            = __float2half(t[tx][ty + r*8]);
}

// ---------------- V transpose: sv[z][1152p x 576] -> svT[z][576 x 1152] ----------------
__global__ __launch_bounds__(256) void k_transV(){
    __shared__ __half t[64][65];
    const int z = blockIdx.z;
    const int r0 = blockIdx.x * 64;
    const int c0 = blockIdx.y * 64;
    const int tx = threadIdx.x & 31, ty = threadIdx.x >> 5;
    const __half* sv = g_sv[z];
    __half* svT = g_svT[z];
    #pragma unroll
    for (int r = 0; r < 8; r++){
        int row = ty + r*8;
        __half2 v = *(const __half2*)(sv + (size_t)(r0 + row)*DH + c0 + tx*2);
        t[row][tx*2]   = __low2half(v);
        t[row][tx*2+1] = __high2half(v);
    }
    __syncthreads();
    #pragma unroll
    for (int c = 0; c < 8; c++){
        int col = ty + c*8;
        __half2 v = __halves2half2(t[tx*2][col], t[tx*2+1][col]);
        *(__half2*)(svT + (size_t)(c0 + col)*KPAD + r0 + tx*2) = v;
    }
}

// ---------------- f16 NT GEMM, f16 acc, pipelined cp.async ----------------
// C[M,N] = A[M,K] @ B[N,K]^T. CTA tile (GM*WM) x (GN*WN). 8 warps.
// K = (KT-1)*64 + KKL*16 (KKL compile-time; KKL=4 => no branch at all).
// OT=0: raw f16 store. OT=1: merged-scores epilogue. OT=2: normalize + fused logits.
template<int OT, int WM, int WN, int GM, int GN, int STAGES, int KKL>
__global__ __launch_bounds__(256, 2) void k_gemmh(
    const __half* __restrict__ A, int lda, int amod, size_t sA,
    const __half* __restrict__ B, int ldb, size_t sB,
    void* __restrict__ Cv, int ldc, size_t sC, int KT,
    const __half* __restrict__ qv, float* __restrict__ out, float* __restrict__ rsum)
{
    constexpr int BM  = GM*WM;
    constexpr int BN  = GN*WN;
    constexpr int ASZ = BM*128;
    constexpr int BSZ = BN*128;
    constexpr int STG = ASZ + BSZ;
    extern __shared__ char smem[];
    const int tid = threadIdx.x, wid = tid>>5, lane = tid&31;
    const int wm = wid % GM, wn = wid / GM;
    const int z = blockIdx.z;
    A += (size_t)(amod ? (z % amod) : z) * sA;
    B += (size_t)z * sB;
    const int m0 = blockIdx.y*BM, n0 = blockIdx.x*BN;
    const uint32_t sbase = smem_u32(smem);
    const int lrow = tid >> 3, lch = tid & 7;

    uint32_t acc[WM/16][WN/8][2];
    #pragma unroll
    for (int i=0;i<WM/16;i++)
        #pragma unroll
        for (int j=0;j<WN/8;j++){ acc[i][j][0]=0u; acc[i][j][1]=0u; }

    auto load_tile = [&](int kt, int buf){
        const __half* Ab = A + (size_t)m0*lda + kt*64;
        const __half* Bb = B + (size_t)n0*ldb + kt*64;
        uint32_t da = sbase + buf*STG;
        uint32_t db = da + ASZ;
        #pragma unroll
        for (int c = 0; c < BM/32; c++){
            int row = lrow + c*32;
            cpa16(da + SW128(row*128 + lch*16), Ab + (size_t)row*lda + lch*8);
        }
        #pragma unroll
        for (int c = 0; c < BN/32; c++){
            int row = lrow + c*32;
            cpa16(db + SW128(row*128 + lch*16), Bb + (size_t)row*ldb + lch*8);
        }
        asm volatile("cp.async.commit_group;");
    };

    auto kk_step = [&](uint32_t sA_, uint32_t sB_, int kk){
        const int colb = kk*32 + ((lane >> 4) << 4);
        uint32_t a[WM/16][4], b[WN/16][4];
        #pragma unroll
        for (int i = 0; i < WM/16; i++)
            ldm4(a[i], sA_ + SW128((wm*WM + i*16 + (lane & 15))*128 + colb));
        #pragma unroll
        for (int j = 0; j < WN/16; j++)
            ldm4(b[j], sB_ + SW128((wn*WN + j*16 + (lane & 15))*128 + colb));
        #pragma unroll
        for (int i = 0; i < WM/16; i++)
            #pragma unroll
            for (int jj = 0; jj < WN/8; jj++)
                mma16816h(acc[i][jj], a[i], b[jj>>1][jj&1], b[jj>>1][2+(jj&1)]);
    };

    #pragma unroll
    for (int s = 0; s < STAGES-1; s++) load_tile(s, s);

    for (int kt = 0; kt < KT; kt++){
        if (kt + STAGES-1 < KT) load_tile(kt + STAGES-1, (kt + STAGES-1) % STAGES);
        if (kt + 1 >= KT)      asm volatile("cp.async.wait_group 0;");
        else if (STAGES == 2 || kt + 2 >= KT) asm volatile("cp.async.wait_group 1;");
        else                   asm volatile("cp.async.wait_group 2;");
        __syncthreads();
        const uint32_t sA_ = sbase + (kt % STAGES)*STG;
        const uint32_t sB_ = sA_ + ASZ;
        if (KKL == 4 || kt < KT-1) {
            #pragma unroll
            for (int kk = 0; kk < 4; kk++) kk_step(sA_, sB_, kk);
        } else {
            #pragma unroll
            for (int kk = 0; kk < KKL; kk++) kk_step(sA_, sB_, kk);
        }
        __syncthreads();
    }

    if (OT == 0) {
        __half* C = (__half*)Cv + (size_t)z * sC;
        #pragma unroll
        for (int i = 0; i < WM/16; i++){
            int r0 = m0 + wm*WM + i*16 + (lane >> 2);
            #pragma unroll
            for (int jj = 0; jj < WN/8; jj++){
                int cc = n0 + wn*WN + jj*8 + (lane & 3)*2;
                *(uint32_t*)(C + (size_t)r0*ldc + cc)     = acc[i][jj][0];
                *(uint32_t*)(C + (size_t)(r0+8)*ldc + cc) = acc[i][jj][1];
            }
        }
    } else if (OT == 1) {
        const int h = z;
        const uint32_t L2E = 0x3dc53dc5u;  // half2(1.4427)
        const int wA = n0 / SKCOL;
        const int bnd = (wA + 1) * SKCOL;
        float rsA[WM/16][2], rsB[WM/16][2];
        #pragma unroll
        for (int i=0;i<WM/16;i++){ rsA[i][0]=0.f; rsA[i][1]=0.f; rsB[i][0]=0.f; rsB[i][1]=0.f; }
        #pragma unroll
        for (int i = 0; i < WM/16; i++){
            int r0 = m0 + wm*WM + i*16 + (lane >> 2);
            #pragma unroll
            for (int jj = 0; jj < WN/8; jj++){
                int cc = n0 + wn*WN + jj*8 + (lane & 3)*2;
                if (cc < NMRG) {
                    int hiw = (cc >= bnd);
                    int w = wA + hiw;
                    int lc = cc - w*SKCOL;
                    __half* C = g_attn[w*2 + h];
                    __half2 m0h = __hmul2(*(__half2*)&acc[i][jj][0], *(__half2*)&L2E);
                    __half2 m1h = __hmul2(*(__half2*)&acc[i][jj][1], *(__half2*)&L2E);
                    uint32_t e0 = h2ex2(*(uint32_t*)&m0h);
                    uint32_t e1 = h2ex2(*(uint32_t*)&m1h);
                    *(uint32_t*)(C + (size_t)r0*KPAD + lc)     = e0;
                    *(uint32_t*)(C + (size_t)(r0+8)*KPAD + lc) = e1;
                    float2 f0 = __half22float2(*(__half2*)&e0);
                    float2 f1 = __half22float2(*(__half2*)&e1);
                    if (hiw) { rsB[i][0] += f0.x + f0.y; rsB[i][1] += f1.x + f1.y; }
                    else     { rsA[i][0] += f0.x + f0.y; rsA[i][1] += f1.x + f1.y; }
                }
            }
        }
        #pragma unroll
        for (int i = 0; i < WM/16; i++){
            int r0 = m0 + wm*WM + i*16 + (lane >> 2);
            #pragma unroll
            for (int rr = 0; rr < 2; rr++){
                float sa = rsA[i][rr], sb = rsB[i][rr];
                sa += __shfl_xor_sync(0xffffffffu, sa, 1);
                sa += __shfl_xor_sync(0xffffffffu, sa, 2);
                sb += __shfl_xor_sync(0xffffffffu, sb, 1);
                sb += __shfl_xor_sync(0xffffffffu, sb, 2);
                if ((lane & 3) == 0) {
                    int row = r0 + rr*8;
                    if (sa != 0.f) atomicAdd(&g_rowsum[wA*2 + h][row], sa);
                    if (sb != 0.f) atomicAdd(&g_rowsum[(wA+1)*2 + h][row], sb);
                }
            }
        }
    } else {
        const int w = z >> 1, h = z & 1;
        const int q0 = m0 / NTUP;
        const int qb = (q0 + 1) * NTUP;
        const float* rz = rsum + (size_t)z * MPAD;
        float s0 = 0.f, s1 = 0.f;
        #pragma unroll
        for (int i = 0; i < WM/16; i++){
            int rb = m0 + wm*WM + i*16 + (lane >> 2);
            #pragma unroll
            for (int rr = 0; rr < 2; rr++){
                int row = rb + rr*8;
                if (row < KROWS) {
                    const float inv = 1.f / rz[row];
                    const __half* qrow = qv + (size_t)row*DIM + h*DH;
                    float part = 0.f;
                    #pragma unroll
                    for (int jj = 0; jj < WN/8; jj++){
                        int cc = n0 + wn*WN + jj*8 + (lane & 3)*2;
                        float2 v = __half22float2(*(__half2*)&acc[i][jj][rr]);
                        float2 q2 = __half22float2(*(const __half2*)(qrow + cc));
                        float d0 = q2.x - v.x*inv;
                        float d1 = q2.y - v.y*inv;
                        part += d0*d0 + d1*d1;
                    }
                    if (row >= qb) s1 += part; else s0 += part;
                }
            }
        }
        float* red = (float*)smem;
        red[tid] = s0; red[256 + tid] = s1;
        __syncthreads();
        #pragma unroll
        for (int st = 128; st > 0; st >>= 1){
            if (tid < st) { red[tid] += red[tid+st]; red[256+tid] += red[256+tid+st]; }
            __syncthreads();
        }
        if (tid == 0 && red[0]   != 0.f) atomicAdd(&out[q0*WAY + w], -red[0]   * (1.f/NTUP));
        if (tid == 1 && q0 + 1 < NQ && red[256] != 0.f)
            atomicAdd(&out[(q0+1)*WAY + w], -red[256] * (1.f/NTUP));
    }
}

// ---------------- tuple combine + bias + LayerNorm (coalesced outputs) ----------------
__global__ __launch_bounds__(192) void k_combine(
    const float* __restrict__ kb, const float* __restrict__ vb,
    const float* __restrict__ lg, const float* __restrict__ lb)
{
    const int bid = blockIdx.x;
    const int v = bid / NTUP, t = bid % NTUP;
    const int tid = threadIdx.x, lane = tid & 31, wrp = tid >> 5;
    __shared__ float redS[6], redQ[6];
    __shared__ int fr[3];
    if (tid < 3) fr[tid] = g_tuples[t*3 + tid];
    __syncthreads();

    const __half2* Pb[3];
    #pragma unroll
    for (int j = 0; j < 3; j++)
        Pb[j] = (const __half2*)(g_P + (size_t)(v*SEQ + fr[j])*6912) + j*1152;

    float2 kv[3], vv[3];
    float lsum = 0.f, lsq = 0.f;
    #pragma unroll
    for (int ii = 0; ii < 3; ii++) {
        int i = tid + ii*192;
        int d0 = 2*i;
        float2 ka = *(const float2*)(kb + d0);
        float2 va = *(const float2*)(vb + d0);
        #pragma unroll
        for (int j = 0; j < 3; j++) {
            float2 pk = __half22float2(Pb[j][i]);
            float2 pv = __half22float2(Pb[j][576 + i]);
            ka.x += pk.x; ka.y += pk.y;
            va.x += pv.x; va.y += pv.y;
        }
        kv[ii] = ka; vv[ii] = va;
        lsum += ka.x + ka.y;
        lsq  += ka.x*ka.x + ka.y*ka.y;
    }
    #pragma unroll
    for (int o = 16; o; o >>= 1) {
        lsum += __shfl_xor_sync(0xffffffffu, lsum, o);
        lsq  += __shfl_xor_sync(0xffffffffu, lsq,  o);
    }
    if (lane == 0) { redS[wrp] = lsum; redQ[wrp] = lsq; }
    __syncthreads();
    if (tid == 0) {
        float s = 0.f, q = 0.f;
        #pragma unroll
        for (int wv = 0; wv < 6; wv++) { s += redS[wv]; q += redQ[wv]; }
        redS[0] = s; redQ[0] = q;
    }
    __syncthreads();
    float mu = redS[0] * (1.f/1152.f);
    float var = redQ[0] * (1.f/1152.f) - mu*mu;
    float rstd = rsqrtf(var + 1e-5f);

    int w = 0, s = 0;
    if (v < NS) { w = v / SHOT; s = v % SHOT; }
    #pragma unroll
    for (int ii = 0; ii < 3; ii++) {
        int i = tid + ii*192;
        int d0 = 2*i;
        int h = (d0 >= DH) ? 1 : 0;
        int dd = d0 - h*DH;
        float2 g = *(const float2*)(lg + d0);
        float2 b = *(const float2*)(lb + d0);
        float ox = ((kv[ii].x - mu)*rstd*g.x + b.x) * RS24;
        float oy = ((kv[ii].y - mu)*rstd*g.y + b.y) * RS24;
        __half2 oh = __floats2half2_rn(ox, oy);
        __half2 vh = __floats2half2_rn(vv[ii].x, vv[ii].y);
        if (v < NS) {
            int row = s*NTUP + t;
            *(__half2*)&g_skzm[h][(size_t)(w*SKCOL + row)*DH + dd] = oh;
            *(__half2*)&g_sv[w*2 + h][(size_t)row*DH + dd] = vh;
        } else {
            *(__half2*)&g_qk[h][(size_t)((v-NS)*NTUP + t)*DH + dd] = oh;
            *(__half2*)&g_qv[(size_t)((v-NS)*NTUP + t)*DIM + d0] = vh;
        }
    }
}

// ---------------- launch ----------------
extern "C" void kernel_launch(void* const* d_in, const int* in_sizes, int n_in,
                              void* d_out, int out_size)
{
    const float* support = (const float*)d_in[0];
    const float* queries = (const float*)d_in[1];
    const float* k_w  = (const float*)d_in[3];
    const float* k_b  = (const float*)d_in[4];
    const float* v_w  = (const float*)d_in[5];
    const float* v_b  = (const float*)d_in[6];
    const float* ln_g = (const float*)d_in[7];
    const float* ln_b = (const float*)d_in[8];
    float* out = (float*)d_out;

    void *pAp, *pWT, *pP, *pQK, *pSKZM, *pSVT, *pATT, *pQV, *pRS;
    cudaGetSymbolAddress(&pAp,   g_Ap);
    cudaGetSymbolAddress(&pWT,   g_wT);
    cudaGetSymbolAddress(&pP,    g_P);
    cudaGetSymbolAddress(&pQK,   g_qk);
    cudaGetSymbolAddress(&pSKZM, g_skzm);
    cudaGetSymbolAddress(&pSVT,  g_svT);
    cudaGetSymbolAddress(&pATT,  g_attn);
    cudaGetSymbolAddress(&pQV,   g_qv);
    cudaGetSymbolAddress(&pRS,   g_rowsum);

    auto gemm_pp = k_gemmh<0,32,64,4,2,3,4>;   // proj, 128x128 tiles (R8-measured fastest)
    auto gemm_sc = k_gemmh<1,32,64,4,2,3,4>;   // merged scores, K exact
    auto gemm_pr = k_gemmh<2,64,48,2,4,2,1>;   // proto, last k-tile = 1 kk (K=1104>=1100)
    cudaFuncSetAttribute(gemm_pp, cudaFuncAttributeMaxDynamicSharedMemorySize, 3*32768);
    cudaFuncSetAttribute(gemm_sc, cudaFuncAttributeMaxDynamicSharedMemorySize, 3*32768);
    cudaFuncSetAttribute(gemm_pr, cudaFuncAttributeMaxDynamicSharedMemorySize, 2*40960);

    // fork/join side stream (capture-legal; proven R8/R10/R12/R13)
    cudaStream_t s1;
    cudaStreamCreateWithFlags(&s1, cudaStreamNonBlocking);
    cudaEvent_t e0, eA, eC, eT;
    cudaEventCreateWithFlags(&e0, cudaEventDisableTiming);
    cudaEventCreateWithFlags(&eA, cudaEventDisableTiming);
    cudaEventCreateWithFlags(&eC, cudaEventDisableTiming);
    cudaEventCreateWithFlags(&eT, cudaEventDisableTiming);

    k_init<<<432, 256>>>(out);
    cudaEventRecord(e0, 0);

    // side stream: A-prep (overlaps transW on main)
    cudaStreamWaitEvent(s1, e0, 0);
    k_prepA<<<NV*SEQ, 128, 0, s1>>>(support, queries);
    cudaEventRecord(eA, s1);

    k_transW<<<dim3(36, 36, 6), 256>>>(k_w, v_w);
    cudaStreamWaitEvent(0, eA, 0);

    // proj: P[1024(900), 6912] = Ap @ wT^T, K=1152, 128x128 tiles, grid 432 (1.46 waves)
    gemm_pp<<<dim3(54, 8, 1), 256, 3*32768>>>(
        (const __half*)pAp, DIM, 1, 0,
        (const __half*)pWT, DIM, 0,
        pP, 6912, 0, 18, nullptr, nullptr, nullptr);

    k_combine<<<NV*NTUP, 192>>>(k_b, v_b, ln_g, ln_b);
    cudaEventRecord(eC, 0);

    // V transpose on side stream, overlapping the scores GEMM
    cudaStreamWaitEvent(s1, eC, 0);
    k_transV<<<dim3(18, 9, WAY*HH), 256, 0, s1>>>();
    cudaEventRecord(eT, s1);

    // merged scores: per h: exp(qk[h] @ skzm[h]^T) -> per-(w,h) attn + rowsum, K=576 exact
    gemm_sc<<<dim3(NMRGP/128, MPAD/128, HH), 256, 3*32768>>>(
        (const __half*)pQK, DH, 2, (size_t)MPAD*DH,
        (const __half*)pSKZM, DH, (size_t)NMRGP*DH,
        nullptr, 0, 0, 9, nullptr, nullptr, nullptr);

    // proto + normalize + fused logits: K = 17*64 + 16 = 1104 >= 1100 (cols 1100-1103 zero)
    cudaStreamWaitEvent(0, eT, 0);
    gemm_pr<<<dim3(3, 86, WAY*HH), 256, 2*40960>>>(
        (const __half*)pATT, KPAD, 0, (size_t)MPAD*KPAD,
        (const __half*)pSVT, KPAD, (size_t)DH*KPAD,
        nullptr, 0, 0, 18, (const __half*)pQV, out, (float*)pRS);
}